// round 7
// baseline (speedup 1.0000x reference)
#include <cuda_runtime.h>

// Problem constants (fixed shapes from the reference)
#define H_IMG 256
#define W_IMG 512
#define NPIX  (H_IMG * W_IMG)   // 131072
#define S_SMP 64
#define TINYF 1e-6f

// 16 lanes cooperate on one pixel; each lane handles 4 samples (16*4 = 64 = S).
#define LANES_PER_PIX 16
#define THREADS_PER_BLOCK 256

__device__ __forceinline__ float fast_ex2(float x) {
    float y;
    asm("ex2.approx.ftz.f32 %0, %1;" : "=f"(y) : "f"(x));
    return y;
}
__device__ __forceinline__ float fast_rcp(float x) {
    float y;
    asm("rcp.approx.ftz.f32 %0, %1;" : "=f"(y) : "f"(x));
    return y;
}

__global__ __launch_bounds__(THREADS_PER_BLOCK)
void shade_kernel(const float* __restrict__ normal,     // (N,3)
                  const float* __restrict__ albedo,     // (N,3)
                  const float* __restrict__ rough,      // (N,1)
                  const float* __restrict__ points,     // (N,3)
                  const float* __restrict__ cam,        // (3,)
                  const float* __restrict__ ldir,       // (N,S,3)
                  const float* __restrict__ dlight,     // (N,S,3)
                  const float* __restrict__ hdir,       // (N,S,3)
                  const float* __restrict__ slight,     // (N,S,3)
                  float* __restrict__ out)              // (N,3)
{
    const int tid  = blockIdx.x * blockDim.x + threadIdx.x;
    const int pix  = tid >> 4;           // 16 lanes per pixel
    const int lane = threadIdx.x & 15;

    // ---- per-pixel setup (replicated across the 16 lanes; amortized over 64 samples) ----
    const float nx = __ldg(normal + 3 * pix + 0);
    const float ny = __ldg(normal + 3 * pix + 1);
    const float nz = __ldg(normal + 3 * pix + 2);

    const float px = __ldg(points + 3 * pix + 0);
    const float py = __ldg(points + 3 * pix + 1);
    const float pz = __ldg(points + 3 * pix + 2);

    const float cx = __ldg(cam + 0);
    const float cy = __ldg(cam + 1);
    const float cz = __ldg(cam + 2);

    float dx = cx - px, dy = cy - py, dz = cz - pz;
    float dd = fmaf(dx, dx, fmaf(dy, dy, dz * dz));
    float invlen = 1.0f / fmaxf(sqrtf(dd), 1e-4f);
    const float vx = dx * invlen, vy = dy * invlen, vz = dz * invlen;

    float ndv = fminf(fmaxf(fmaf(nx, vx, fmaf(ny, vy, nz * vz)), 0.0f), 1.0f);

    const float r   = __ldg(rough + pix);
    const float k   = (r + 1.0f) * (r + 1.0f) * 0.125f;   // k in [1/8, 1/2]
    const float omk = 1.0f - k;
    const float G   = ndv / fmaxf(fmaf(ndv, omk, k), TINYF);  // g1_ndv (per-pixel)
    const float c4  = 4.0f * ndv;

    // accumulators
    float dA0 = 0.f, dA1 = 0.f, dA2 = 0.f;   // sum dl * ndl_d
    float sA0 = 0.f, sA1 = 0.f, sA2 = 0.f;   // sum sl * (f*ndl^2*vdh / (D1*D2*D3))

    // per-sample body
    auto proc = [&](float lx, float ly, float lz,
                    float dlx, float dly, float dlz,
                    float hx, float hy, float hz,
                    float slx, float sly, float slz) {
        // diffuse: ndl_d = clamp(dot(n, l), 0, 1); unit vectors -> upper clip is eps-level
        float ndl_d = fmaxf(fmaf(nx, lx, fmaf(ny, ly, nz * lz)), 0.0f);
        dA0 = fmaf(dlx, ndl_d, dA0);
        dA1 = fmaf(dly, ndl_d, dA1);
        dA2 = fmaf(dlz, ndl_d, dA2);

        // specular
        float vdh = fmaxf(fmaf(hx, vx, fmaf(hy, vy, hz * vz)), 0.0f);
        float t   = vdh + vdh;
        float lsx = fmaf(t, hx, -vx);
        float lsy = fmaf(t, hy, -vy);
        float lsz = fmaf(t, hz, -vz);            // |l_spec| == 1 exactly
        float ndl = fmaxf(fmaf(nx, lsx, fmaf(ny, lsy, nz * lsz)), 0.0f);
        float ndh = fmaxf(fmaf(nx, hx, fmaf(ny, hy, nz * hz)), 0.0f);

        float e = fmaf(-5.55472f, vdh, -6.98316f) * vdh;       // in [-12.6, 0]
        float f = fmaf(0.96f, fast_ex2(e), 0.04f);

        float D1 = fmaxf(fmaf(ndl, omk, k), TINYF);            // >= 0.125
        float D2 = fmaxf(ndl * c4, TINYF);                     // max(4*ndl*ndv, TINY)
        float D3 = fmaxf(ndh, TINYF);
        float rinv = fast_rcp(D1 * (D2 * D3));                 // one MUFU for all 3 denoms

        float scale = (f * vdh) * (ndl * ndl) * rinv;
        sA0 = fmaf(slx, scale, sA0);
        sA1 = fmaf(sly, scale, sA1);
        sA2 = fmaf(slz, scale, sA2);
    };

    // ---- streaming loads: 4 samples = 12 floats = 3 x float4 per array (16B aligned) ----
    const int base = pix * (S_SMP * 3) + lane * 12;   // max ~25.2M, fits int

    const float4* Lp = reinterpret_cast<const float4*>(ldir   + base);
    const float4* Dp = reinterpret_cast<const float4*>(dlight + base);
    const float4* Hp = reinterpret_cast<const float4*>(hdir   + base);
    const float4* Sp = reinterpret_cast<const float4*>(slight + base);

    float4 L0 = __ldcs(Lp + 0), L1 = __ldcs(Lp + 1), L2 = __ldcs(Lp + 2);
    float4 D0 = __ldcs(Dp + 0), D1v = __ldcs(Dp + 1), D2v = __ldcs(Dp + 2);
    float4 H0 = __ldcs(Hp + 0), H1 = __ldcs(Hp + 1), H2 = __ldcs(Hp + 2);
    float4 S0 = __ldcs(Sp + 0), S1 = __ldcs(Sp + 1), S2 = __ldcs(Sp + 2);

    // unpack 4 samples (components at 3j, 3j+1, 3j+2 within the 12 floats)
    proc(L0.x, L0.y, L0.z,  D0.x, D0.y, D0.z,  H0.x, H0.y, H0.z,  S0.x, S0.y, S0.z);
    proc(L0.w, L1.x, L1.y,  D0.w, D1v.x, D1v.y, H0.w, H1.x, H1.y,  S0.w, S1.x, S1.y);
    proc(L1.z, L1.w, L2.x,  D1v.z, D1v.w, D2v.x, H1.z, H1.w, H2.x,  S1.z, S1.w, S2.x);
    proc(L2.y, L2.z, L2.w,  D2v.y, D2v.z, D2v.w, H2.y, H2.z, H2.w,  S2.y, S2.z, S2.w);

    // ---- reduce over the 16-lane group (xor offsets < 16 stay within the half-warp) ----
    #pragma unroll
    for (int off = 8; off > 0; off >>= 1) {
        dA0 += __shfl_xor_sync(0xffffffffu, dA0, off);
        dA1 += __shfl_xor_sync(0xffffffffu, dA1, off);
        dA2 += __shfl_xor_sync(0xffffffffu, dA2, off);
        sA0 += __shfl_xor_sync(0xffffffffu, sA0, off);
        sA1 += __shfl_xor_sync(0xffffffffu, sA1, off);
        sA2 += __shfl_xor_sync(0xffffffffu, sA2, off);
    }

    if (lane == 0) {
        const float a0 = __ldg(albedo + 3 * pix + 0);
        const float a1 = __ldg(albedo + 3 * pix + 1);
        const float a2 = __ldg(albedo + 3 * pix + 2);
        const float dscale = 2.0f / (float)S_SMP;        // (a/pi)*2*pi/S
        const float sscale = (4.0f * G) / (float)S_SMP;  // 4*g1_ndv/S
        out[3 * pix + 0] = fmaf(a0 * dscale, dA0, sscale * sA0);
        out[3 * pix + 1] = fmaf(a1 * dscale, dA1, sscale * sA1);
        out[3 * pix + 2] = fmaf(a2 * dscale, dA2, sscale * sA2);
    }
}

extern "C" void kernel_launch(void* const* d_in, const int* in_sizes, int n_in,
                              void* d_out, int out_size) {
    const float* normal  = (const float*)d_in[0];
    const float* albedo  = (const float*)d_in[1];
    const float* rough   = (const float*)d_in[2];
    const float* points  = (const float*)d_in[3];
    const float* cam     = (const float*)d_in[4];
    const float* ldir    = (const float*)d_in[5];
    const float* dlight  = (const float*)d_in[6];
    const float* hdir    = (const float*)d_in[7];
    const float* slight  = (const float*)d_in[8];
    float* out = (float*)d_out;

    const int total_threads = NPIX * LANES_PER_PIX;             // 2,097,152
    const int blocks = total_threads / THREADS_PER_BLOCK;       // 8192

    shade_kernel<<<blocks, THREADS_PER_BLOCK>>>(
        normal, albedo, rough, points, cam,
        ldir, dlight, hdir, slight, out);
}

// round 9
// speedup vs baseline: 1.0111x; 1.0111x over previous
#include <cuda_runtime.h>

// Problem constants (fixed shapes from the reference)
#define H_IMG 256
#define W_IMG 512
#define NPIX  (H_IMG * W_IMG)   // 131072
#define S_SMP 64
#define TINYF 1e-6f

// 16 lanes cooperate on one pixel; each lane handles 4 samples (16*4 = 64 = S).
#define LANES_PER_PIX 16
#define TPB 256
#define NBLK (148 * 3)                     // persistent-ish: 3 CTAs/SM resident
#define TOTALT (NPIX * LANES_PER_PIX)      // 2,097,152 logical threads
#define STRIDE (NBLK * TPB)                // 113,664

__device__ __forceinline__ float fast_ex2(float x) {
    float y;
    asm("ex2.approx.ftz.f32 %0, %1;" : "=f"(y) : "f"(x));
    return y;
}
__device__ __forceinline__ float fast_rcp(float x) {
    float y;
    asm("rcp.approx.ftz.f32 %0, %1;" : "=f"(y) : "f"(x));
    return y;
}

__global__ __launch_bounds__(TPB, 3)
void shade_kernel(const float* __restrict__ normal,     // (N,3)
                  const float* __restrict__ albedo,     // (N,3)
                  const float* __restrict__ rough,      // (N,1)
                  const float* __restrict__ points,     // (N,3)
                  const float* __restrict__ cam,        // (3,)
                  const float* __restrict__ ldir,       // (N,S,3)
                  const float* __restrict__ dlight,     // (N,S,3)
                  const float* __restrict__ hdir,       // (N,S,3)
                  const float* __restrict__ slight,     // (N,S,3)
                  float* __restrict__ out)              // (N,3)
{
    const float cx = __ldg(cam + 0);
    const float cy = __ldg(cam + 1);
    const float cz = __ldg(cam + 2);

    int idx  = blockIdx.x * TPB + threadIdx.x;   // < STRIDE <= TOTALT always
    int pix  = idx >> 4;
    int lane = idx & 15;

    // ---- prologue: issue first tile's streaming loads ----
    int base = pix * (S_SMP * 3) + lane * 12;    // 16B-aligned float4 base

    float4 L0 = __ldcs((const float4*)(ldir   + base) + 0);
    float4 L1 = __ldcs((const float4*)(ldir   + base) + 1);
    float4 L2 = __ldcs((const float4*)(ldir   + base) + 2);
    float4 D0 = __ldcs((const float4*)(dlight + base) + 0);
    float4 D1 = __ldcs((const float4*)(dlight + base) + 1);
    float4 D2 = __ldcs((const float4*)(dlight + base) + 2);
    float4 H0 = __ldcs((const float4*)(hdir   + base) + 0);
    float4 H1 = __ldcs((const float4*)(hdir   + base) + 1);
    float4 H2 = __ldcs((const float4*)(hdir   + base) + 2);
    float4 S0 = __ldcs((const float4*)(slight + base) + 0);
    float4 S1 = __ldcs((const float4*)(slight + base) + 1);
    float4 S2 = __ldcs((const float4*)(slight + base) + 2);

    while (true) {
        // ---- per-pixel setup (L1-resident loads; overlaps in-flight bulk loads) ----
        const float nx = __ldg(normal + 3 * pix + 0);
        const float ny = __ldg(normal + 3 * pix + 1);
        const float nz = __ldg(normal + 3 * pix + 2);
        const float px = __ldg(points + 3 * pix + 0);
        const float py = __ldg(points + 3 * pix + 1);
        const float pz = __ldg(points + 3 * pix + 2);
        const float r  = __ldg(rough + pix);

        float dx = cx - px, dy = cy - py, dz = cz - pz;
        float dd = fmaf(dx, dx, fmaf(dy, dy, dz * dz));
        float invlen = 1.0f / fmaxf(sqrtf(dd), 1e-4f);
        const float vx = dx * invlen, vy = dy * invlen, vz = dz * invlen;

        float ndv = fminf(fmaxf(fmaf(nx, vx, fmaf(ny, vy, nz * vz)), 0.0f), 1.0f);

        const float k   = (r + 1.0f) * (r + 1.0f) * 0.125f;     // k in [1/8, 1/2]
        const float omk = 1.0f - k;
        const float G   = ndv / fmaxf(fmaf(ndv, omk, k), TINYF); // g1_ndv
        const float c4  = 4.0f * ndv;

        float dA0 = 0.f, dA1 = 0.f, dA2 = 0.f;
        float sA0 = 0.f, sA1 = 0.f, sA2 = 0.f;

        auto proc = [&](float lx, float ly, float lz,
                        float dlx, float dly, float dlz,
                        float hx, float hy, float hz,
                        float slx, float sly, float slz) {
            // diffuse (unit vectors -> upper clip is eps-level, omitted)
            float ndl_d = fmaxf(fmaf(nx, lx, fmaf(ny, ly, nz * lz)), 0.0f);
            dA0 = fmaf(dlx, ndl_d, dA0);
            dA1 = fmaf(dly, ndl_d, dA1);
            dA2 = fmaf(dlz, ndl_d, dA2);

            // specular
            float vdh = fmaxf(fmaf(hx, vx, fmaf(hy, vy, hz * vz)), 0.0f);
            float t   = vdh + vdh;
            float lsx = fmaf(t, hx, -vx);
            float lsy = fmaf(t, hy, -vy);
            float lsz = fmaf(t, hz, -vz);
            float ndl = fmaxf(fmaf(nx, lsx, fmaf(ny, lsy, nz * lsz)), 0.0f);
            float ndh = fmaxf(fmaf(nx, hx, fmaf(ny, hy, nz * hz)), 0.0f);

            float e = fmaf(-5.55472f, vdh, -6.98316f) * vdh;
            float f = fmaf(0.96f, fast_ex2(e), 0.04f);

            float Q1 = fmaxf(fmaf(ndl, omk, k), TINYF);     // >= 0.125
            float Q2 = fmaxf(ndl * c4, TINYF);
            float Q3 = fmaxf(ndh, TINYF);
            float rinv = fast_rcp(Q1 * (Q2 * Q3));          // one MUFU for all 3 denoms

            float scale = (f * vdh) * (ndl * ndl) * rinv;
            sA0 = fmaf(slx, scale, sA0);
            sA1 = fmaf(sly, scale, sA1);
            sA2 = fmaf(slz, scale, sA2);
        };

        // consume buffers (4 samples)
        proc(L0.x, L0.y, L0.z,  D0.x, D0.y, D0.z,  H0.x, H0.y, H0.z,  S0.x, S0.y, S0.z);
        proc(L0.w, L1.x, L1.y,  D0.w, D1.x, D1.y,  H0.w, H1.x, H1.y,  S0.w, S1.x, S1.y);
        proc(L1.z, L1.w, L2.x,  D1.z, D1.w, D2.x,  H1.z, H1.w, H2.x,  S1.z, S1.w, S2.x);
        proc(L2.y, L2.z, L2.w,  D2.y, D2.z, D2.w,  H2.y, H2.z, H2.w,  S2.y, S2.z, S2.w);

        // ---- pipeline: issue next tile's loads BEFORE the reduction/store ----
        int nidx = idx + STRIDE;
        bool last = (nidx >= TOTALT);           // warp-uniform (STRIDE, TOTALT mult. of 32)
        int npix = 0, nlane = 0;
        if (!last) {
            npix  = nidx >> 4;
            nlane = nidx & 15;
            int nbase = npix * (S_SMP * 3) + nlane * 12;
            L0 = __ldcs((const float4*)(ldir   + nbase) + 0);
            L1 = __ldcs((const float4*)(ldir   + nbase) + 1);
            L2 = __ldcs((const float4*)(ldir   + nbase) + 2);
            D0 = __ldcs((const float4*)(dlight + nbase) + 0);
            D1 = __ldcs((const float4*)(dlight + nbase) + 1);
            D2 = __ldcs((const float4*)(dlight + nbase) + 2);
            H0 = __ldcs((const float4*)(hdir   + nbase) + 0);
            H1 = __ldcs((const float4*)(hdir   + nbase) + 1);
            H2 = __ldcs((const float4*)(hdir   + nbase) + 2);
            S0 = __ldcs((const float4*)(slight + nbase) + 0);
            S1 = __ldcs((const float4*)(slight + nbase) + 1);
            S2 = __ldcs((const float4*)(slight + nbase) + 2);
        }

        // ---- 16-lane reduction (overlaps next loads' latency) ----
        #pragma unroll
        for (int off = 8; off > 0; off >>= 1) {
            dA0 += __shfl_xor_sync(0xffffffffu, dA0, off);
            dA1 += __shfl_xor_sync(0xffffffffu, dA1, off);
            dA2 += __shfl_xor_sync(0xffffffffu, dA2, off);
            sA0 += __shfl_xor_sync(0xffffffffu, sA0, off);
            sA1 += __shfl_xor_sync(0xffffffffu, sA1, off);
            sA2 += __shfl_xor_sync(0xffffffffu, sA2, off);
        }

        if (lane == 0) {
            const float a0 = __ldg(albedo + 3 * pix + 0);
            const float a1 = __ldg(albedo + 3 * pix + 1);
            const float a2 = __ldg(albedo + 3 * pix + 2);
            const float dscale = 2.0f / (float)S_SMP;
            const float sscale = (4.0f * G) / (float)S_SMP;
            out[3 * pix + 0] = fmaf(a0 * dscale, dA0, sscale * sA0);
            out[3 * pix + 1] = fmaf(a1 * dscale, dA1, sscale * sA1);
            out[3 * pix + 2] = fmaf(a2 * dscale, dA2, sscale * sA2);
        }

        if (last) break;
        idx = nidx; pix = npix; lane = nlane;
    }
}

extern "C" void kernel_launch(void* const* d_in, const int* in_sizes, int n_in,
                              void* d_out, int out_size) {
    const float* normal  = (const float*)d_in[0];
    const float* albedo  = (const float*)d_in[1];
    const float* rough   = (const float*)d_in[2];
    const float* points  = (const float*)d_in[3];
    const float* cam     = (const float*)d_in[4];
    const float* ldir    = (const float*)d_in[5];
    const float* dlight  = (const float*)d_in[6];
    const float* hdir    = (const float*)d_in[7];
    const float* slight  = (const float*)d_in[8];
    float* out = (float*)d_out;

    shade_kernel<<<NBLK, TPB>>>(
        normal, albedo, rough, points, cam,
        ldir, dlight, hdir, slight, out);
}